// round 6
// baseline (speedup 1.0000x reference)
#include <cuda_runtime.h>
#include <cuda_bf16.h>
#include <stdint.h>

#define BHN 16
#define LEN 2048
#define DIM 64
#define RN  4
#define NB2 16
#define CH  128
#define NK  256

typedef unsigned long long ull;

// ---------------- scratch (device globals; allocation-free) ----------------
__device__ float  g_qn  [BHN][LEN][DIM];
__device__ float  g_rmn [BHN][DIM][64];
__device__ int    g_hash[BHN][RN][LEN];
__device__ int    g_hidx[BHN][RN][LEN];
__device__ int    g_oidx[BHN][RN][LEN];
__device__ int    g_pc  [BHN][LEN];          // packed chunk per round
__device__ int    g_ppc [BHN][LEN];          // packed (chunk-1)&15 per round
__device__ float  g_sc  [BHN][RN][LEN][NK];  // adjusted scores, then p (in-place)
__device__ float  g_attn[BHN][RN][LEN][DIM]; // per-round attn, sorted order

__constant__ float c_log4[4] = {0.0f, 0.6931471805599453f, 1.0986122886681098f, 1.3862943611198906f};

// ---------------- f32x2 helpers ----------------
__device__ __forceinline__ ull dup2(float v) {
    ull r;
    asm("mov.b64 %0, {%1, %1};" : "=l"(r) : "r"(__float_as_uint(v)));
    return r;
}
__device__ __forceinline__ ull fma2(ull a, ull b, ull c) {
    ull d;
    asm("fma.rn.f32x2 %0, %1, %2, %3;" : "=l"(d) : "l"(a), "l"(b), "l"(c));
    return d;
}
__device__ __forceinline__ float2 unpk2(ull v) {
    unsigned int lo, hi;
    asm("mov.b64 {%0, %1}, %2;" : "=r"(lo), "=r"(hi) : "l"(v));
    float2 f; f.x = __uint_as_float(lo); f.y = __uint_as_float(hi);
    return f;
}

// fast exp on the FMA pipe — R2's exact version
__device__ __forceinline__ float fexp(float x) {
    x = fmaxf(x, -87.0f);
    float t = fmaf(x, 1.4426950408889634f, 12582912.0f);
    int n = __float_as_int(t) - 0x4B400000;
    float fi = t - 12582912.0f;
    float z = fmaf(fi, -0.6931471805599453f, x);
    float p = 8.3333337e-3f;
    p = fmaf(p, z, 4.1666668e-2f);
    p = fmaf(p, z, 0.16666667f);
    p = fmaf(p, z, 0.5f);
    p = fmaf(p, z, 1.0f);
    p = fmaf(p, z, 1.0f);
    return p * __int_as_float((n + 127) << 23);
}

// ---------------- K0: normalize rand_matrix columns ----------------
__global__ void k_rmn(const float* __restrict__ rm) {
    int b = blockIdx.x;
    int j = threadIdx.x;
    float s = 0.f;
    for (int d = 0; d < DIM; d++) {
        float v = rm[(size_t)(b * DIM + d) * 64 + j];
        s += v * v;
    }
    float inv = rsqrtf(s);
    for (int d = 0; d < DIM; d++)
        g_rmn[b][d][j] = rm[(size_t)(b * DIM + d) * 64 + j] * inv;
}

// ---------------- K1: normalize q + hashes ----------------
__global__ void __launch_bounds__(128) k_hash(const float* __restrict__ q) {
    int b = blockIdx.y;
    __shared__ float s_rm[DIM * 64];
    int tid = threadIdx.x;
    const float4* rsrc = (const float4*)&g_rmn[b][0][0];
    for (int t = tid; t < DIM * 64 / 4; t += 128) ((float4*)s_rm)[t] = rsrc[t];
    __syncthreads();

    int l = blockIdx.x * 128 + tid;
    float qv[DIM];
    const float4* qp = (const float4*)&q[((size_t)b * LEN + l) * DIM];
#pragma unroll
    for (int t = 0; t < 16; t++) {
        float4 v = qp[t];
        qv[4 * t] = v.x; qv[4 * t + 1] = v.y; qv[4 * t + 2] = v.z; qv[4 * t + 3] = v.w;
    }
    float ss = 0.f;
#pragma unroll
    for (int d = 0; d < DIM; d++) ss += qv[d] * qv[d];
    float inv = rsqrtf(ss);
#pragma unroll
    for (int d = 0; d < DIM; d++) qv[d] *= inv;
    float4* qd = (float4*)&g_qn[b][l][0];
#pragma unroll
    for (int t = 0; t < 16; t++)
        qd[t] = make_float4(qv[4 * t], qv[4 * t + 1], qv[4 * t + 2], qv[4 * t + 3]);

    for (int r = 0; r < RN; r++) {
        float bp = -1e30f, bn = -1e30f;
        int bpi = 0, bni = 0;
        for (int k = 0; k < 16; k++) {
            float acc = 0.f;
#pragma unroll
            for (int d = 0; d < DIM; d++) acc += qv[d] * s_rm[d * 64 + r * 16 + k];
            if (acc > bp)  { bp = acc;  bpi = k; }
            if (-acc > bn) { bn = -acc; bni = k; }
        }
        g_hash[b][r][l] = (bn > bp) ? (16 + bni) : bpi;
    }
}

// ---------------- K2: stable counting sort per (b,r) ----------------
__global__ void __launch_bounds__(256) k_sort() {
    int b = blockIdx.x >> 2, r = blockIdx.x & 3;
    __shared__ int hist[32][257];
    __shared__ int base[32];
    int t = threadIdx.x;
#pragma unroll
    for (int v = 0; v < 32; v++) hist[v][t] = 0;
    __syncthreads();
    int h[8];
#pragma unroll
    for (int e = 0; e < 8; e++) {
        h[e] = g_hash[b][r][t * 8 + e];
        hist[h[e]][t]++;
    }
    __syncthreads();
    if (t < 32) {
        int run = 0;
        for (int i = 0; i < 256; i++) { int x = hist[t][i]; hist[t][i] = run; run += x; }
        base[t] = run;
    }
    __syncthreads();
    if (t == 0) {
        int run = 0;
        for (int v = 0; v < 32; v++) { int x = base[v]; base[v] = run; run += x; }
    }
    __syncthreads();
#pragma unroll
    for (int e = 0; e < 8; e++) {
        int l = t * 8 + e, v = h[e];
        int off = hist[v][t];
        hist[v][t] = off + 1;
        int pos = base[v] + off;
        g_hidx[b][r][pos] = l;
        g_oidx[b][r][l] = pos;
    }
}

// ---------------- K2.5: pack per-token chunk ids (cur + prev) ----------------
__global__ void __launch_bounds__(256) k_pack() {
    int gid = blockIdx.x * 256 + threadIdx.x;
    int l = gid & (LEN - 1);
    int b = gid >> 11;
    int v = 0, w = 0;
#pragma unroll
    for (int r = 0; r < RN; r++) {
        int n = (g_oidx[b][r][l] >> 7) & 15;
        v |= n << (8 * r);
        w |= ((n + 15) & 15) << (8 * r);
    }
    g_pc[b][l] = v;
    g_ppc[b][l] = w;
}

// ---------------- K3: masked score GEMM + fused count adjust ----------------
// thread (tx,ty): i = tx*8 + e (contiguous 8), j = ty*8 + 2f+{0,1}
__device__ __forceinline__ void ld_dk(const float* ks, int j0, int i0, int d,
                                      ull kv[4], float qv[8]) {
    const float* rw = ks + d * NK;
    ulonglong2 t0 = *(const ulonglong2*)(rw + j0);
    ulonglong2 t1 = *(const ulonglong2*)(rw + j0 + 4);
    kv[0] = t0.x; kv[1] = t0.y; kv[2] = t1.x; kv[3] = t1.y;
    float4 q0 = *(const float4*)(rw + CH + i0);
    float4 q1 = *(const float4*)(rw + CH + i0 + 4);
    qv[0] = q0.x; qv[1] = q0.y; qv[2] = q0.z; qv[3] = q0.w;
    qv[4] = q1.x; qv[5] = q1.y; qv[6] = q1.z; qv[7] = q1.w;
}
__device__ __forceinline__ void fma_dk(ull acc[8][4], const ull kv[4], const float qv[8]) {
#pragma unroll
    for (int e = 0; e < 8; e++) {
        ull qp = dup2(qv[e]);
#pragma unroll
        for (int f = 0; f < 4; f++) acc[e][f] = fma2(qp, kv[f], acc[e][f]);
    }
}

__global__ void __launch_bounds__(512) k_scores() {
    int n = blockIdx.x, r = blockIdx.y, b = blockIdx.z;
    extern __shared__ float sm3[];
    float* ks    = sm3;                        // [64][256]
    int*   kidx  = (int*)(sm3 + DIM * NK);     // [256]
    int*   khash = kidx + NK;                  // [256]
    int*   kpc   = khash + NK;                 // [256]
    int*   kppc  = kpc + NK;                   // [256]
    int tid = threadIdx.y * 16 + threadIdx.x;
    int prevbase = ((n + NB2 - 1) & (NB2 - 1)) * CH;

    for (int j = tid; j < NK; j += 512) {
        int keypos = (j < CH) ? (prevbase + j) : (n * CH + j - CH);
        int ki = g_hidx[b][r][keypos];
        kidx[j] = ki;
        khash[j] = g_hash[b][r][ki];
        kpc[j]  = g_pc[b][ki];
        kppc[j] = g_ppc[b][ki];
    }
    __syncthreads();
    for (int tsk = tid; tsk < NK * 16; tsk += 512) {
        int c = tsk >> 8, j = tsk & 255;
        float4 v = *(const float4*)&g_qn[b][kidx[j]][c * 4];
        ks[(c * 4 + 0) * NK + j] = v.x;
        ks[(c * 4 + 1) * NK + j] = v.y;
        ks[(c * 4 + 2) * NK + j] = v.z;
        ks[(c * 4 + 3) * NK + j] = v.w;
    }
    __syncthreads();

    int tx = threadIdx.x;       // i0 = tx*8
    int ty = threadIdx.y;       // j0 = ty*8
    int j0 = ty * 8;
    int i0 = tx * 8;
    ull acc[8][4];
#pragma unroll
    for (int e = 0; e < 8; e++)
#pragma unroll
        for (int f = 0; f < 4; f++) acc[e][f] = 0ull;

    ull kvA[4], kvB[4];
    float qA[8], qB[8];
    ld_dk(ks, j0, i0, 0, kvA, qA);
#pragma unroll 2
    for (int d = 0; d < DIM; d += 2) {
        ld_dk(ks, j0, i0, d + 1, kvB, qB);
        fma_dk(acc, kvA, qA);
        ld_dk(ks, j0, i0, (d + 2) & 63, kvA, qA);
        fma_dk(acc, kvB, qB);
    }

#pragma unroll
    for (int e = 0; e < 8; e++) {
        int i = i0 + e;
        int qidx = kidx[CH + i];
        int qh   = khash[CH + i];
        int np   = kpc[CH + i];
        int pp   = kppc[CH + i];
        float o[8];
#pragma unroll
        for (int f = 0; f < 4; f++) {
            float2 v = unpk2(acc[e][f]);
            o[2 * f] = v.x; o[2 * f + 1] = v.y;
        }
#pragma unroll
        for (int g = 0; g < 8; g++) {
            int j = j0 + g;
            float s = o[g] * 0.125f;
            int kj = kidx[j];
            if (qidx == kj)                       s = -100000.0f;
            else if (qidx < kj || qh != khash[j]) s = -1000000000.0f;
            unsigned m = __vcmpeq4((unsigned)kpc[j], (unsigned)np)
                       | __vcmpeq4((unsigned)kpc[j], (unsigned)pp);
            s -= c_log4[(__popc(m) >> 3) - 1];
            o[g] = s;
        }
        float4* dst = (float4*)&g_sc[b][r][n * CH + i][j0];
        dst[0] = make_float4(o[0], o[1], o[2], o[3]);
        dst[1] = make_float4(o[4], o[5], o[6], o[7]);
    }
}

// ---------------- K4: joint softmax over pre-adjusted scores (in-place) ----------------
__global__ void __launch_bounds__(512) k_softmax() {
    int b = blockIdx.y;
    int warp = threadIdx.x >> 5, lane = threadIdx.x & 31;
#pragma unroll 1
    for (int it = 0; it < 16; it++) {
        int l = blockIdx.x * 256 + it * 16 + warp;
        int srs[RN];
        float adj[RN][8];
        float mx = -3.4e38f;
#pragma unroll
        for (int r = 0; r < RN; r++) {
            srs[r] = g_oidx[b][r][l];
            const float* srow = &g_sc[b][r][srs[r]][0];
#pragma unroll
            for (int c = 0; c < 8; c++) {
                float a = srow[c * 32 + lane];
                adj[r][c] = a;
                mx = fmaxf(mx, a);
            }
        }
#pragma unroll
        for (int o = 16; o; o >>= 1) mx = fmaxf(mx, __shfl_xor_sync(0xffffffffu, mx, o));
        float sum = 0.f;
#pragma unroll
        for (int r = 0; r < RN; r++)
#pragma unroll
            for (int c = 0; c < 8; c++) {
                float e = fexp(adj[r][c] - mx);
                adj[r][c] = e;
                sum += e;
            }
#pragma unroll
        for (int o = 16; o; o >>= 1) sum += __shfl_xor_sync(0xffffffffu, sum, o);
        float inv = 1.0f / sum;
#pragma unroll
        for (int r = 0; r < RN; r++) {
            float* srow = &g_sc[b][r][srs[r]][0];
#pragma unroll
            for (int c = 0; c < 8; c++) srow[c * 32 + lane] = adj[r][c] * inv;
        }
    }
}

// ---------------- K5: p @ v_sorted per (b,r,chunk) ----------------
__global__ void __launch_bounds__(256) k_av(const float* __restrict__ v) {
    int n = blockIdx.x, r = blockIdx.y, b = blockIdx.z;
    extern __shared__ float s_vs[];  // [256][64]
    int tid = threadIdx.x;
    int prevbase = ((n + NB2 - 1) & (NB2 - 1)) * CH;
    for (int idx = tid; idx < NK * 16; idx += 256) {
        int j = idx >> 4, f = idx & 15;
        int keypos = (j < CH) ? (prevbase + j) : (n * CH + j - CH);
        int ki = g_hidx[b][r][keypos];
        *(float4*)&s_vs[j * 64 + f * 4] = *(const float4*)&v[((size_t)b * LEN + ki) * DIM + f * 4];
    }
    __syncthreads();

    int warp = tid >> 5, lane = tid & 31;
    int i0 = warp * 16;
    ull acc[16];
#pragma unroll
    for (int i = 0; i < 16; i++) acc[i] = 0ull;
    const float* prow = &g_sc[b][r][n * CH + i0][0];

    // prefetch p tiles one jj-group ahead (accumulation order per acc[i] unchanged)
    float4 pA[16], pB[16];
#pragma unroll
    for (int i = 0; i < 16; i++) pA[i] = *(const float4*)&prow[i * NK + 0];
#pragma unroll 1
    for (int jj = 0; jj < NK; jj += 8) {
        ull v2[8];
#pragma unroll
        for (int t = 0; t < 8; t++)
            v2[t] = *(const ull*)&s_vs[(jj + t) * 64 + lane * 2];
#pragma unroll
        for (int i = 0; i < 16; i++) pB[i] = *(const float4*)&prow[i * NK + jj + 4];
#pragma unroll
        for (int i = 0; i < 16; i++) {
            acc[i] = fma2(dup2(pA[i].x), v2[0], acc[i]);
            acc[i] = fma2(dup2(pA[i].y), v2[1], acc[i]);
            acc[i] = fma2(dup2(pA[i].z), v2[2], acc[i]);
            acc[i] = fma2(dup2(pA[i].w), v2[3], acc[i]);
        }
#pragma unroll
        for (int i = 0; i < 16; i++) pA[i] = *(const float4*)&prow[i * NK + ((jj + 8) & 255)];
#pragma unroll
        for (int i = 0; i < 16; i++) {
            acc[i] = fma2(dup2(pB[i].x), v2[4], acc[i]);
            acc[i] = fma2(dup2(pB[i].y), v2[5], acc[i]);
            acc[i] = fma2(dup2(pB[i].z), v2[6], acc[i]);
            acc[i] = fma2(dup2(pB[i].w), v2[7], acc[i]);
        }
    }
#pragma unroll
    for (int i = 0; i < 16; i++)
        *(ull*)&g_attn[b][r][n * CH + i0 + i][lane * 2] = acc[i];
}

// ---------------- K6: gather rounds back to original order, sum ----------------
__global__ void __launch_bounds__(256) k_out(float* __restrict__ out) {
    int gid = blockIdx.x * 256 + threadIdx.x;
    int dq = gid & 15;
    int l = (gid >> 4) & (LEN - 1);
    int b = gid >> 15;
    float4 s = make_float4(0.f, 0.f, 0.f, 0.f);
#pragma unroll
    for (int r = 0; r < RN; r++) {
        int sIdx = g_oidx[b][r][l];
        float4 a = *(const float4*)&g_attn[b][r][sIdx][dq * 4];
        s.x += a.x; s.y += a.y; s.z += a.z; s.w += a.w;
    }
    *(float4*)&out[((size_t)b * LEN + l) * DIM + dq * 4] = s;
}

// ---------------- launch ----------------
extern "C" void kernel_launch(void* const* d_in, const int* in_sizes, int n_in,
                              void* d_out, int out_size) {
    const float* q  = (const float*)d_in[0];
    const float* v  = (const float*)d_in[1];
    const float* rm = (const float*)d_in[2];
    float* out = (float*)d_out;

    const int smem3 = DIM * NK * 4 + 4 * NK * 4;  // 69632
    const int smem5 = NK * DIM * 4;               // 65536
    cudaFuncSetAttribute(k_scores, cudaFuncAttributeMaxDynamicSharedMemorySize, smem3);
    cudaFuncSetAttribute(k_av,     cudaFuncAttributeMaxDynamicSharedMemorySize, smem5);

    k_rmn<<<BHN, 64>>>(rm);
    k_hash<<<dim3(LEN / 128, BHN), 128>>>(q);
    k_sort<<<BHN * RN, 256>>>();
    k_pack<<<BHN * LEN / 256, 256>>>();
    k_scores<<<dim3(NB2, RN, BHN), dim3(16, 32), smem3>>>();
    k_softmax<<<dim3(LEN / 256, BHN), 512>>>();
    k_av<<<dim3(NB2, RN, BHN), 256, smem5>>>(v);
    k_out<<<(BHN * LEN * 16) / 256, 256>>>(out);
}

// round 8
// speedup vs baseline: 1.2158x; 1.2158x over previous
#include <cuda_runtime.h>
#include <cuda_bf16.h>
#include <stdint.h>

#define BHN 16
#define LEN 2048
#define DIM 64
#define RN  4
#define NB2 16
#define CH  128
#define NK  256
#define XSTR 72   // bf16 elements per staged row (64 data + 8 pad)

typedef unsigned long long ull;

// ---------------- scratch (device globals; allocation-free) ----------------
__device__ float  g_qn  [BHN][LEN][DIM];
__device__ float  g_rmn [BHN][DIM][64];
__device__ int    g_hash[BHN][RN][LEN];
__device__ int    g_hidx[BHN][RN][LEN];
__device__ int    g_oidx[BHN][RN][LEN];
__device__ int    g_pc  [BHN][LEN];
__device__ int    g_ppc [BHN][LEN];
__device__ float  g_sc  [BHN][RN][LEN][NK];  // adjusted scores, then p (in-place)
__device__ float  g_attn[BHN][RN][LEN][DIM];

__constant__ float c_log4[4] = {0.0f, 0.6931471805599453f, 1.0986122886681098f, 1.3862943611198906f};

// ---------------- f32x2 helpers ----------------
__device__ __forceinline__ ull dup2(float v) {
    ull r; asm("mov.b64 %0, {%1, %1};" : "=l"(r) : "r"(__float_as_uint(v))); return r;
}
__device__ __forceinline__ ull fma2(ull a, ull b, ull c) {
    ull d; asm("fma.rn.f32x2 %0, %1, %2, %3;" : "=l"(d) : "l"(a), "l"(b), "l"(c)); return d;
}

// fast exp on the FMA pipe — R2's exact version
__device__ __forceinline__ float fexp(float x) {
    x = fmaxf(x, -87.0f);
    float t = fmaf(x, 1.4426950408889634f, 12582912.0f);
    int n = __float_as_int(t) - 0x4B400000;
    float fi = t - 12582912.0f;
    float z = fmaf(fi, -0.6931471805599453f, x);
    float p = 8.3333337e-3f;
    p = fmaf(p, z, 4.1666668e-2f);
    p = fmaf(p, z, 0.16666667f);
    p = fmaf(p, z, 0.5f);
    p = fmaf(p, z, 1.0f);
    p = fmaf(p, z, 1.0f);
    return p * __int_as_float((n + 127) << 23);
}

// ---------------- mma.sync bf16 m16n8k16 ----------------
__device__ __forceinline__ void mma_bf16(float* c, const uint32_t* a, uint32_t b0, uint32_t b1) {
    asm volatile(
        "mma.sync.aligned.m16n8k16.row.col.f32.bf16.bf16.f32 "
        "{%0,%1,%2,%3}, {%4,%5,%6,%7}, {%8,%9}, {%0,%1,%2,%3};"
        : "+f"(c[0]), "+f"(c[1]), "+f"(c[2]), "+f"(c[3])
        : "r"(a[0]), "r"(a[1]), "r"(a[2]), "r"(a[3]), "r"(b0), "r"(b1));
}

// ---------------- K0: normalize rand_matrix columns ----------------
__global__ void k_rmn(const float* __restrict__ rm) {
    int b = blockIdx.x;
    int j = threadIdx.x;
    float s = 0.f;
    for (int d = 0; d < DIM; d++) {
        float v = rm[(size_t)(b * DIM + d) * 64 + j];
        s += v * v;
    }
    float inv = rsqrtf(s);
    for (int d = 0; d < DIM; d++)
        g_rmn[b][d][j] = rm[(size_t)(b * DIM + d) * 64 + j] * inv;
}

// ---------------- K1: normalize q + hashes ----------------
__global__ void __launch_bounds__(128) k_hash(const float* __restrict__ q) {
    int b = blockIdx.y;
    __shared__ float s_rm[DIM * 64];
    int tid = threadIdx.x;
    const float4* rsrc = (const float4*)&g_rmn[b][0][0];
    for (int t = tid; t < DIM * 64 / 4; t += 128) ((float4*)s_rm)[t] = rsrc[t];
    __syncthreads();

    int l = blockIdx.x * 128 + tid;
    float qv[DIM];
    const float4* qp = (const float4*)&q[((size_t)b * LEN + l) * DIM];
#pragma unroll
    for (int t = 0; t < 16; t++) {
        float4 v = qp[t];
        qv[4 * t] = v.x; qv[4 * t + 1] = v.y; qv[4 * t + 2] = v.z; qv[4 * t + 3] = v.w;
    }
    float ss = 0.f;
#pragma unroll
    for (int d = 0; d < DIM; d++) ss += qv[d] * qv[d];
    float inv = rsqrtf(ss);
#pragma unroll
    for (int d = 0; d < DIM; d++) qv[d] *= inv;
    float4* qd = (float4*)&g_qn[b][l][0];
#pragma unroll
    for (int t = 0; t < 16; t++)
        qd[t] = make_float4(qv[4 * t], qv[4 * t + 1], qv[4 * t + 2], qv[4 * t + 3]);

    for (int r = 0; r < RN; r++) {
        float bp = -1e30f, bn = -1e30f;
        int bpi = 0, bni = 0;
        for (int k = 0; k < 16; k++) {
            float acc = 0.f;
#pragma unroll
            for (int d = 0; d < DIM; d++) acc += qv[d] * s_rm[d * 64 + r * 16 + k];
            if (acc > bp)  { bp = acc;  bpi = k; }
            if (-acc > bn) { bn = -acc; bni = k; }
        }
        g_hash[b][r][l] = (bn > bp) ? (16 + bni) : bpi;
    }
}

// ---------------- K2: stable counting sort per (b,r) ----------------
__global__ void __launch_bounds__(256) k_sort() {
    int b = blockIdx.x >> 2, r = blockIdx.x & 3;
    __shared__ int hist[32][257];
    __shared__ int base[32];
    int t = threadIdx.x;
#pragma unroll
    for (int v = 0; v < 32; v++) hist[v][t] = 0;
    __syncthreads();
    int h[8];
#pragma unroll
    for (int e = 0; e < 8; e++) {
        h[e] = g_hash[b][r][t * 8 + e];
        hist[h[e]][t]++;
    }
    __syncthreads();
    if (t < 32) {
        int run = 0;
        for (int i = 0; i < 256; i++) { int x = hist[t][i]; hist[t][i] = run; run += x; }
        base[t] = run;
    }
    __syncthreads();
    if (t == 0) {
        int run = 0;
        for (int v = 0; v < 32; v++) { int x = base[v]; base[v] = run; run += x; }
    }
    __syncthreads();
#pragma unroll
    for (int e = 0; e < 8; e++) {
        int l = t * 8 + e, v = h[e];
        int off = hist[v][t];
        hist[v][t] = off + 1;
        int pos = base[v] + off;
        g_hidx[b][r][pos] = l;
        g_oidx[b][r][l] = pos;
    }
}

// ---------------- K2.5: pack per-token chunk ids ----------------
__global__ void __launch_bounds__(256) k_pack() {
    int gid = blockIdx.x * 256 + threadIdx.x;
    int l = gid & (LEN - 1);
    int b = gid >> 11;
    int v = 0, w = 0;
#pragma unroll
    for (int r = 0; r < RN; r++) {
        int n = (g_oidx[b][r][l] >> 7) & 15;
        v |= n << (8 * r);
        w |= ((n + 15) & 15) << (8 * r);
    }
    g_pc[b][l] = v;
    g_ppc[b][l] = w;
}

// ---------------- K3: bf16-split mma.sync score GEMM + masks + count adjust ----------------
// smem: kidx@0, khash@1024, kpc@2048, kppc@3072 (ints),
//       xh @4096 (256*72 bf16 = 36864B), xl @40960. total 77824B
#define SM3_TOTAL (4096 + 2 * NK * XSTR * 2)

__global__ void __launch_bounds__(512) k_scores() {
    int n = blockIdx.x, r = blockIdx.y, b = blockIdx.z;
    extern __shared__ char sm3[];
    int* kidx  = (int*)sm3;
    int* khash = kidx + NK;
    int* kpc   = khash + NK;
    int* kppc  = kpc + NK;
    __nv_bfloat16* xh = (__nv_bfloat16*)(sm3 + 4096);
    __nv_bfloat16* xl = (__nv_bfloat16*)(sm3 + 4096 + NK * XSTR * 2);
    int tid = threadIdx.x;
    int prevbase = ((n + NB2 - 1) & (NB2 - 1)) * CH;

    for (int j = tid; j < NK; j += 512) {
        int keypos = (j < CH) ? (prevbase + j) : (n * CH + j - CH);
        int ki = g_hidx[b][r][keypos];
        kidx[j]  = ki;
        khash[j] = g_hash[b][r][ki];
        kpc[j]   = g_pc[b][ki];
        kppc[j]  = g_ppc[b][ki];
    }
    __syncthreads();

    // stage hi/lo bf16 tiles: row 0..127 = keys, 128..255 = queries (this chunk)
    for (int t = tid; t < NK * 16; t += 512) {
        int row = t >> 4, cg = t & 15;
        float4 v = *(const float4*)&g_qn[b][kidx[row]][cg * 4];
        __nv_bfloat16 h0 = __float2bfloat16(v.x);
        __nv_bfloat16 h1 = __float2bfloat16(v.y);
        __nv_bfloat16 h2 = __float2bfloat16(v.z);
        __nv_bfloat16 h3 = __float2bfloat16(v.w);
        __nv_bfloat16 l0 = __float2bfloat16(v.x - __bfloat162float(h0));
        __nv_bfloat16 l1 = __float2bfloat16(v.y - __bfloat162float(h1));
        __nv_bfloat16 l2 = __float2bfloat16(v.z - __bfloat162float(h2));
        __nv_bfloat16 l3 = __float2bfloat16(v.w - __bfloat162float(h3));
        uint2 hv, lv;
        hv.x = ((uint32_t)__bfloat16_as_ushort(h1) << 16) | __bfloat16_as_ushort(h0);
        hv.y = ((uint32_t)__bfloat16_as_ushort(h3) << 16) | __bfloat16_as_ushort(h2);
        lv.x = ((uint32_t)__bfloat16_as_ushort(l1) << 16) | __bfloat16_as_ushort(l0);
        lv.y = ((uint32_t)__bfloat16_as_ushort(l3) << 16) | __bfloat16_as_ushort(l2);
        *(uint2*)&xh[row * XSTR + cg * 4] = hv;
        *(uint2*)&xl[row * XSTR + cg * 4] = lv;
    }
    __syncthreads();

    int wid = tid >> 5, lane = tid & 31;
    int wm = wid >> 1, wn = wid & 1;
    int i0 = wm * 16, j0 = wn * 128;
    int g = lane >> 2, t4 = lane & 3;

    float acc[16][4];
#pragma unroll
    for (int nt = 0; nt < 16; nt++)
#pragma unroll
        for (int c = 0; c < 4; c++) acc[nt][c] = 0.f;

    const __nv_bfloat16* Ah = xh + (CH + i0) * XSTR;
    const __nv_bfloat16* Al = xl + (CH + i0) * XSTR;
#pragma unroll
    for (int ks = 0; ks < 4; ks++) {
        int k0 = ks * 16 + 2 * t4;
        uint32_t ah[4], al[4];
        ah[0] = *(const uint32_t*)&Ah[g * XSTR + k0];
        ah[1] = *(const uint32_t*)&Ah[(g + 8) * XSTR + k0];
        ah[2] = *(const uint32_t*)&Ah[g * XSTR + k0 + 8];
        ah[3] = *(const uint32_t*)&Ah[(g + 8) * XSTR + k0 + 8];
        al[0] = *(const uint32_t*)&Al[g * XSTR + k0];
        al[1] = *(const uint32_t*)&Al[(g + 8) * XSTR + k0];
        al[2] = *(const uint32_t*)&Al[g * XSTR + k0 + 8];
        al[3] = *(const uint32_t*)&Al[(g + 8) * XSTR + k0 + 8];
#pragma unroll
        for (int nt = 0; nt < 16; nt++) {
            int rowb = (j0 + nt * 8 + g) * XSTR + k0;
            uint32_t bh0 = *(const uint32_t*)&xh[rowb];
            uint32_t bh1 = *(const uint32_t*)&xh[rowb + 8];
            uint32_t bl0 = *(const uint32_t*)&xl[rowb];
            uint32_t bl1 = *(const uint32_t*)&xl[rowb + 8];
            mma_bf16(acc[nt], ah, bh0, bh1);
            mma_bf16(acc[nt], ah, bl0, bl1);
            mma_bf16(acc[nt], al, bh0, bh1);
        }
    }

    // epilogue: c0,c1 -> row i0+g cols (j, j+1); c2,c3 -> row i0+g+8
    int ia = i0 + g, ib = i0 + g + 8;
    int qidxa = kidx[CH + ia], qha = khash[CH + ia], npa = kpc[CH + ia], ppa = kppc[CH + ia];
    int qidxb = kidx[CH + ib], qhb = khash[CH + ib], npb = kpc[CH + ib], ppb = kppc[CH + ib];
    float* rowa = &g_sc[b][r][n * CH + ia][0];
    float* rowb = &g_sc[b][r][n * CH + ib][0];
#pragma unroll
    for (int nt = 0; nt < 16; nt++) {
        int j = j0 + nt * 8 + 2 * t4;
        int kj0 = kidx[j],  kh0 = khash[j],  kc0 = kpc[j],  kp0 = kppc[j];
        int kj1 = kidx[j+1],kh1 = khash[j+1],kc1 = kpc[j+1],kp1 = kppc[j+1];
        float o00 = acc[nt][0] * 0.125f, o01 = acc[nt][1] * 0.125f;
        float o10 = acc[nt][2] * 0.125f, o11 = acc[nt][3] * 0.125f;
        if (qidxa == kj0)                      o00 = -100000.0f;
        else if (qidxa < kj0 || qha != kh0)    o00 = -1000000000.0f;
        if (qidxa == kj1)                      o01 = -100000.0f;
        else if (qidxa < kj1 || qha != kh1)    o01 = -1000000000.0f;
        if (qidxb == kj0)                      o10 = -100000.0f;
        else if (qidxb < kj0 || qhb != kh0)    o10 = -1000000000.0f;
        if (qidxb == kj1)                      o11 = -100000.0f;
        else if (qidxb < kj1 || qhb != kh1)    o11 = -1000000000.0f;
        unsigned m;
        m = __vcmpeq4((unsigned)kc0, (unsigned)npa) | __vcmpeq4((unsigned)kc0, (unsigned)ppa);
        o00 -= c_log4[(__popc(m) >> 3) - 1];
        m = __vcmpeq4((unsigned)kc1, (unsigned)npa) | __vcmpeq4((unsigned)kc1, (unsigned)ppa);
        o01 -= c_log4[(__popc(m) >> 3) - 1];
        m = __vcmpeq4((unsigned)kc0, (unsigned)npb) | __vcmpeq4((unsigned)kc0, (unsigned)ppb);
        o10 -= c_log4[(__popc(m) >> 3) - 1];
        m = __vcmpeq4((unsigned)kc1, (unsigned)npb) | __vcmpeq4((unsigned)kc1, (unsigned)ppb);
        o11 -= c_log4[(__popc(m) >> 3) - 1];
        *(float2*)&rowa[j] = make_float2(o00, o01);
        *(float2*)&rowb[j] = make_float2(o10, o11);
    }
}

// ---------------- K4: joint softmax over pre-adjusted scores (in-place) ----------------
__global__ void __launch_bounds__(512) k_softmax() {
    int b = blockIdx.y;
    int warp = threadIdx.x >> 5, lane = threadIdx.x & 31;
#pragma unroll 1
    for (int it = 0; it < 16; it++) {
        int l = blockIdx.x * 256 + it * 16 + warp;
        int srs[RN];
        float adj[RN][8];
        float mx = -3.4e38f;
#pragma unroll
        for (int r = 0; r < RN; r++) {
            srs[r] = g_oidx[b][r][l];
            const float* srow = &g_sc[b][r][srs[r]][0];
#pragma unroll
            for (int c = 0; c < 8; c++) {
                float a = srow[c * 32 + lane];
                adj[r][c] = a;
                mx = fmaxf(mx, a);
            }
        }
#pragma unroll
        for (int o = 16; o; o >>= 1) mx = fmaxf(mx, __shfl_xor_sync(0xffffffffu, mx, o));
        float sum = 0.f;
#pragma unroll
        for (int r = 0; r < RN; r++)
#pragma unroll
            for (int c = 0; c < 8; c++) {
                float e = fexp(adj[r][c] - mx);
                adj[r][c] = e;
                sum += e;
            }
#pragma unroll
        for (int o = 16; o; o >>= 1) sum += __shfl_xor_sync(0xffffffffu, sum, o);
        float inv = 1.0f / sum;
#pragma unroll
        for (int r = 0; r < RN; r++) {
            float* srow = &g_sc[b][r][srs[r]][0];
#pragma unroll
            for (int c = 0; c < 8; c++) srow[c * 32 + lane] = adj[r][c] * inv;
        }
    }
}

// ---------------- K5: p @ v_sorted per (b,r,chunk) — R5 verbatim ----------------
__global__ void __launch_bounds__(256) k_av(const float* __restrict__ v) {
    int n = blockIdx.x, r = blockIdx.y, b = blockIdx.z;
    extern __shared__ float s_vs[];  // [256][64]
    int tid = threadIdx.x;
    int prevbase = ((n + NB2 - 1) & (NB2 - 1)) * CH;
    for (int idx = tid; idx < NK * 16; idx += 256) {
        int j = idx >> 4, f = idx & 15;
        int keypos = (j < CH) ? (prevbase + j) : (n * CH + j - CH);
        int ki = g_hidx[b][r][keypos];
        *(float4*)&s_vs[j * 64 + f * 4] = *(const float4*)&v[((size_t)b * LEN + ki) * DIM + f * 4];
    }
    __syncthreads();

    int warp = tid >> 5, lane = tid & 31;
    int i0 = warp * 16;
    ull acc[16];
#pragma unroll
    for (int i = 0; i < 16; i++) acc[i] = 0ull;
    const float* prow = &g_sc[b][r][n * CH + i0][0];
    for (int jj = 0; jj < NK; jj += 4) {
        ull v2[4];
#pragma unroll
        for (int t = 0; t < 4; t++)
            v2[t] = *(const ull*)&s_vs[(jj + t) * 64 + lane * 2];
#pragma unroll
        for (int i = 0; i < 16; i++) {
            float4 p4 = *(const float4*)&prow[i * NK + jj];
            acc[i] = fma2(dup2(p4.x), v2[0], acc[i]);
            acc[i] = fma2(dup2(p4.y), v2[1], acc[i]);
            acc[i] = fma2(dup2(p4.z), v2[2], acc[i]);
            acc[i] = fma2(dup2(p4.w), v2[3], acc[i]);
        }
    }
#pragma unroll
    for (int i = 0; i < 16; i++)
        *(ull*)&g_attn[b][r][n * CH + i0 + i][lane * 2] = acc[i];
}

// ---------------- K6: gather rounds back to original order, sum ----------------
__global__ void __launch_bounds__(256) k_out(float* __restrict__ out) {
    int gid = blockIdx.x * 256 + threadIdx.x;
    int dq = gid & 15;
    int l = (gid >> 4) & (LEN - 1);
    int b = gid >> 15;
    float4 s = make_float4(0.f, 0.f, 0.f, 0.f);
#pragma unroll
    for (int r = 0; r < RN; r++) {
        int sIdx = g_oidx[b][r][l];
        float4 a = *(const float4*)&g_attn[b][r][sIdx][dq * 4];
        s.x += a.x; s.y += a.y; s.z += a.z; s.w += a.w;
    }
    *(float4*)&out[((size_t)b * LEN + l) * DIM + dq * 4] = s;
}

// ---------------- launch ----------------
extern "C" void kernel_launch(void* const* d_in, const int* in_sizes, int n_in,
                              void* d_out, int out_size) {
    const float* q  = (const float*)d_in[0];
    const float* v  = (const float*)d_in[1];
    const float* rm = (const float*)d_in[2];
    float* out = (float*)d_out;

    const int smem5 = NK * DIM * 4;  // 65536
    cudaFuncSetAttribute(k_scores, cudaFuncAttributeMaxDynamicSharedMemorySize, SM3_TOTAL);
    cudaFuncSetAttribute(k_av,     cudaFuncAttributeMaxDynamicSharedMemorySize, smem5);

    k_rmn<<<BHN, 64>>>(rm);
    k_hash<<<dim3(LEN / 128, BHN), 128>>>(q);
    k_sort<<<BHN * RN, 256>>>();
    k_pack<<<BHN * LEN / 256, 256>>>();
    k_scores<<<dim3(NB2, RN, BHN), 512, SM3_TOTAL>>>();
    k_softmax<<<dim3(LEN / 256, BHN), 512>>>();
    k_av<<<dim3(NB2, RN, BHN), 256, smem5>>>(v);
    k_out<<<(BHN * LEN * 16) / 256, 256>>>(out);
}

// round 9
// speedup vs baseline: 1.7388x; 1.4301x over previous
#include <cuda_runtime.h>
#include <cuda_bf16.h>
#include <stdint.h>

#define BHN 16
#define LEN 2048
#define DIM 64
#define RN  4
#define NB2 16
#define CH  128
#define NK  256
#define XSTR 72    // k_scores staged row stride (bf16)
#define VSTR 264   // k_av vT row stride (bf16)

typedef unsigned long long ull;

// ---------------- scratch (device globals; allocation-free) ----------------
__device__ float  g_qn  [BHN][LEN][DIM];
__device__ float  g_rmn [BHN][DIM][64];
__device__ int    g_hash[BHN][RN][LEN];
__device__ int    g_hidx[BHN][RN][LEN];
__device__ int    g_oidx[BHN][RN][LEN];
__device__ int    g_pc  [BHN][LEN];
__device__ int    g_ppc [BHN][LEN];
__device__ float  g_sc  [BHN][RN][LEN][NK];  // adjusted scores, then p (in-place)
__device__ float  g_attn[BHN][RN][LEN][DIM];

__constant__ float c_log4[4] = {0.0f, 0.6931471805599453f, 1.0986122886681098f, 1.3862943611198906f};

// fast exp on the FMA pipe — R2's exact version
__device__ __forceinline__ float fexp(float x) {
    x = fmaxf(x, -87.0f);
    float t = fmaf(x, 1.4426950408889634f, 12582912.0f);
    int n = __float_as_int(t) - 0x4B400000;
    float fi = t - 12582912.0f;
    float z = fmaf(fi, -0.6931471805599453f, x);
    float p = 8.3333337e-3f;
    p = fmaf(p, z, 4.1666668e-2f);
    p = fmaf(p, z, 0.16666667f);
    p = fmaf(p, z, 0.5f);
    p = fmaf(p, z, 1.0f);
    p = fmaf(p, z, 1.0f);
    return p * __int_as_float((n + 127) << 23);
}

// ---------------- mma.sync bf16 m16n8k16 ----------------
__device__ __forceinline__ void mma_bf16(float* c, const uint32_t* a, uint32_t b0, uint32_t b1) {
    asm volatile(
        "mma.sync.aligned.m16n8k16.row.col.f32.bf16.bf16.f32 "
        "{%0,%1,%2,%3}, {%4,%5,%6,%7}, {%8,%9}, {%0,%1,%2,%3};"
        : "+f"(c[0]), "+f"(c[1]), "+f"(c[2]), "+f"(c[3])
        : "r"(a[0]), "r"(a[1]), "r"(a[2]), "r"(a[3]), "r"(b0), "r"(b1));
}

// split float2 -> packed bf16 hi (x) and lo (y); low half = .x
__device__ __forceinline__ uint2 split2(float2 f) {
    __nv_bfloat16 h0 = __float2bfloat16(f.x);
    __nv_bfloat16 h1 = __float2bfloat16(f.y);
    __nv_bfloat16 l0 = __float2bfloat16(f.x - __bfloat162float(h0));
    __nv_bfloat16 l1 = __float2bfloat16(f.y - __bfloat162float(h1));
    uint2 r;
    r.x = ((uint32_t)__bfloat16_as_ushort(h1) << 16) | __bfloat16_as_ushort(h0);
    r.y = ((uint32_t)__bfloat16_as_ushort(l1) << 16) | __bfloat16_as_ushort(l0);
    return r;
}

// ---------------- K0: normalize rand_matrix columns ----------------
__global__ void k_rmn(const float* __restrict__ rm) {
    int b = blockIdx.x;
    int j = threadIdx.x;
    float s = 0.f;
    for (int d = 0; d < DIM; d++) {
        float v = rm[(size_t)(b * DIM + d) * 64 + j];
        s += v * v;
    }
    float inv = rsqrtf(s);
    for (int d = 0; d < DIM; d++)
        g_rmn[b][d][j] = rm[(size_t)(b * DIM + d) * 64 + j] * inv;
}

// ---------------- K1: normalize q + hashes ----------------
__global__ void __launch_bounds__(128) k_hash(const float* __restrict__ q) {
    int b = blockIdx.y;
    __shared__ float s_rm[DIM * 64];
    int tid = threadIdx.x;
    const float4* rsrc = (const float4*)&g_rmn[b][0][0];
    for (int t = tid; t < DIM * 64 / 4; t += 128) ((float4*)s_rm)[t] = rsrc[t];
    __syncthreads();

    int l = blockIdx.x * 128 + tid;
    float qv[DIM];
    const float4* qp = (const float4*)&q[((size_t)b * LEN + l) * DIM];
#pragma unroll
    for (int t = 0; t < 16; t++) {
        float4 v = qp[t];
        qv[4 * t] = v.x; qv[4 * t + 1] = v.y; qv[4 * t + 2] = v.z; qv[4 * t + 3] = v.w;
    }
    float ss = 0.f;
#pragma unroll
    for (int d = 0; d < DIM; d++) ss += qv[d] * qv[d];
    float inv = rsqrtf(ss);
#pragma unroll
    for (int d = 0; d < DIM; d++) qv[d] *= inv;
    float4* qd = (float4*)&g_qn[b][l][0];
#pragma unroll
    for (int t = 0; t < 16; t++)
        qd[t] = make_float4(qv[4 * t], qv[4 * t + 1], qv[4 * t + 2], qv[4 * t + 3]);

    for (int r = 0; r < RN; r++) {
        float bp = -1e30f, bn = -1e30f;
        int bpi = 0, bni = 0;
        for (int k = 0; k < 16; k++) {
            float acc = 0.f;
#pragma unroll
            for (int d = 0; d < DIM; d++) acc += qv[d] * s_rm[d * 64 + r * 16 + k];
            if (acc > bp)  { bp = acc;  bpi = k; }
            if (-acc > bn) { bn = -acc; bni = k; }
        }
        g_hash[b][r][l] = (bn > bp) ? (16 + bni) : bpi;
    }
}

// ---------------- K2: stable counting sort per (b,r) ----------------
__global__ void __launch_bounds__(256) k_sort() {
    int b = blockIdx.x >> 2, r = blockIdx.x & 3;
    __shared__ int hist[32][257];
    __shared__ int base[32];
    int t = threadIdx.x;
#pragma unroll
    for (int v = 0; v < 32; v++) hist[v][t] = 0;
    __syncthreads();
    int h[8];
#pragma unroll
    for (int e = 0; e < 8; e++) {
        h[e] = g_hash[b][r][t * 8 + e];
        hist[h[e]][t]++;
    }
    __syncthreads();
    if (t < 32) {
        int run = 0;
        for (int i = 0; i < 256; i++) { int x = hist[t][i]; hist[t][i] = run; run += x; }
        base[t] = run;
    }
    __syncthreads();
    if (t == 0) {
        int run = 0;
        for (int v = 0; v < 32; v++) { int x = base[v]; base[v] = run; run += x; }
    }
    __syncthreads();
#pragma unroll
    for (int e = 0; e < 8; e++) {
        int l = t * 8 + e, v = h[e];
        int off = hist[v][t];
        hist[v][t] = off + 1;
        int pos = base[v] + off;
        g_hidx[b][r][pos] = l;
        g_oidx[b][r][l] = pos;
    }
}

// ---------------- K2.5: pack per-token chunk ids ----------------
__global__ void __launch_bounds__(256) k_pack() {
    int gid = blockIdx.x * 256 + threadIdx.x;
    int l = gid & (LEN - 1);
    int b = gid >> 11;
    int v = 0, w = 0;
#pragma unroll
    for (int r = 0; r < RN; r++) {
        int n = (g_oidx[b][r][l] >> 7) & 15;
        v |= n << (8 * r);
        w |= ((n + 15) & 15) << (8 * r);
    }
    g_pc[b][l] = v;
    g_ppc[b][l] = w;
}

// ---------------- K3: bf16-split mma.sync score GEMM (R8 verbatim) ----------------
#define SM3_TOTAL (4096 + 2 * NK * XSTR * 2)

__global__ void __launch_bounds__(512) k_scores() {
    int n = blockIdx.x, r = blockIdx.y, b = blockIdx.z;
    extern __shared__ char sm3[];
    int* kidx  = (int*)sm3;
    int* khash = kidx + NK;
    int* kpc   = khash + NK;
    int* kppc  = kpc + NK;
    __nv_bfloat16* xh = (__nv_bfloat16*)(sm3 + 4096);
    __nv_bfloat16* xl = (__nv_bfloat16*)(sm3 + 4096 + NK * XSTR * 2);
    int tid = threadIdx.x;
    int prevbase = ((n + NB2 - 1) & (NB2 - 1)) * CH;

    for (int j = tid; j < NK; j += 512) {
        int keypos = (j < CH) ? (prevbase + j) : (n * CH + j - CH);
        int ki = g_hidx[b][r][keypos];
        kidx[j]  = ki;
        khash[j] = g_hash[b][r][ki];
        kpc[j]   = g_pc[b][ki];
        kppc[j]  = g_ppc[b][ki];
    }
    __syncthreads();

    for (int t = tid; t < NK * 16; t += 512) {
        int row = t >> 4, cg = t & 15;
        float4 v = *(const float4*)&g_qn[b][kidx[row]][cg * 4];
        uint2 p0 = split2(make_float2(v.x, v.y));
        uint2 p1 = split2(make_float2(v.z, v.w));
        *(uint2*)&xh[row * XSTR + cg * 4] = make_uint2(p0.x, p1.x);
        *(uint2*)&xl[row * XSTR + cg * 4] = make_uint2(p0.y, p1.y);
    }
    __syncthreads();

    int wid = tid >> 5, lane = tid & 31;
    int wm = wid >> 1, wn = wid & 1;
    int i0 = wm * 16, j0 = wn * 128;
    int g = lane >> 2, t4 = lane & 3;

    float acc[16][4];
#pragma unroll
    for (int nt = 0; nt < 16; nt++)
#pragma unroll
        for (int c = 0; c < 4; c++) acc[nt][c] = 0.f;

    const __nv_bfloat16* Ah = xh + (CH + i0) * XSTR;
    const __nv_bfloat16* Al = xl + (CH + i0) * XSTR;
#pragma unroll
    for (int ks = 0; ks < 4; ks++) {
        int k0 = ks * 16 + 2 * t4;
        uint32_t ah[4], al[4];
        ah[0] = *(const uint32_t*)&Ah[g * XSTR + k0];
        ah[1] = *(const uint32_t*)&Ah[(g + 8) * XSTR + k0];
        ah[2] = *(const uint32_t*)&Ah[g * XSTR + k0 + 8];
        ah[3] = *(const uint32_t*)&Ah[(g + 8) * XSTR + k0 + 8];
        al[0] = *(const uint32_t*)&Al[g * XSTR + k0];
        al[1] = *(const uint32_t*)&Al[(g + 8) * XSTR + k0];
        al[2] = *(const uint32_t*)&Al[g * XSTR + k0 + 8];
        al[3] = *(const uint32_t*)&Al[(g + 8) * XSTR + k0 + 8];
#pragma unroll
        for (int nt = 0; nt < 16; nt++) {
            int rowb = (j0 + nt * 8 + g) * XSTR + k0;
            uint32_t bh0 = *(const uint32_t*)&xh[rowb];
            uint32_t bh1 = *(const uint32_t*)&xh[rowb + 8];
            uint32_t bl0 = *(const uint32_t*)&xl[rowb];
            uint32_t bl1 = *(const uint32_t*)&xl[rowb + 8];
            mma_bf16(acc[nt], ah, bh0, bh1);
            mma_bf16(acc[nt], ah, bl0, bl1);
            mma_bf16(acc[nt], al, bh0, bh1);
        }
    }

    int ia = i0 + g, ib = i0 + g + 8;
    int qidxa = kidx[CH + ia], qha = khash[CH + ia], npa = kpc[CH + ia], ppa = kppc[CH + ia];
    int qidxb = kidx[CH + ib], qhb = khash[CH + ib], npb = kpc[CH + ib], ppb = kppc[CH + ib];
    float* rowa = &g_sc[b][r][n * CH + ia][0];
    float* rowb = &g_sc[b][r][n * CH + ib][0];
#pragma unroll
    for (int nt = 0; nt < 16; nt++) {
        int j = j0 + nt * 8 + 2 * t4;
        int kj0 = kidx[j],  kh0 = khash[j],  kc0 = kpc[j];
        int kj1 = kidx[j+1],kh1 = khash[j+1],kc1 = kpc[j+1];
        float o00 = acc[nt][0] * 0.125f, o01 = acc[nt][1] * 0.125f;
        float o10 = acc[nt][2] * 0.125f, o11 = acc[nt][3] * 0.125f;
        if (qidxa == kj0)                      o00 = -100000.0f;
        else if (qidxa < kj0 || qha != kh0)    o00 = -1000000000.0f;
        if (qidxa == kj1)                      o01 = -100000.0f;
        else if (qidxa < kj1 || qha != kh1)    o01 = -1000000000.0f;
        if (qidxb == kj0)                      o10 = -100000.0f;
        else if (qidxb < kj0 || qhb != kh0)    o10 = -1000000000.0f;
        if (qidxb == kj1)                      o11 = -100000.0f;
        else if (qidxb < kj1 || qhb != kh1)    o11 = -1000000000.0f;
        unsigned m;
        m = __vcmpeq4((unsigned)kc0, (unsigned)npa) | __vcmpeq4((unsigned)kc0, (unsigned)ppa);
        o00 -= c_log4[(__popc(m) >> 3) - 1];
        m = __vcmpeq4((unsigned)kc1, (unsigned)npa) | __vcmpeq4((unsigned)kc1, (unsigned)ppa);
        o01 -= c_log4[(__popc(m) >> 3) - 1];
        m = __vcmpeq4((unsigned)kc0, (unsigned)npb) | __vcmpeq4((unsigned)kc0, (unsigned)ppb);
        o10 -= c_log4[(__popc(m) >> 3) - 1];
        m = __vcmpeq4((unsigned)kc1, (unsigned)npb) | __vcmpeq4((unsigned)kc1, (unsigned)ppb);
        o11 -= c_log4[(__popc(m) >> 3) - 1];
        *(float2*)&rowa[j] = make_float2(o00, o01);
        *(float2*)&rowb[j] = make_float2(o10, o11);
    }
}

// ---------------- K4: joint softmax over pre-adjusted scores (in-place) ----------------
__global__ void __launch_bounds__(512) k_softmax() {
    int b = blockIdx.y;
    int warp = threadIdx.x >> 5, lane = threadIdx.x & 31;
#pragma unroll 1
    for (int it = 0; it < 16; it++) {
        int l = blockIdx.x * 256 + it * 16 + warp;
        int srs[RN];
        float adj[RN][8];
        float mx = -3.4e38f;
#pragma unroll
        for (int r = 0; r < RN; r++) {
            srs[r] = g_oidx[b][r][l];
            const float* srow = &g_sc[b][r][srs[r]][0];
#pragma unroll
            for (int c = 0; c < 8; c++) {
                float a = srow[c * 32 + lane];
                adj[r][c] = a;
                mx = fmaxf(mx, a);
            }
        }
#pragma unroll
        for (int o = 16; o; o >>= 1) mx = fmaxf(mx, __shfl_xor_sync(0xffffffffu, mx, o));
        float sum = 0.f;
#pragma unroll
        for (int r = 0; r < RN; r++)
#pragma unroll
            for (int c = 0; c < 8; c++) {
                float e = fexp(adj[r][c] - mx);
                adj[r][c] = e;
                sum += e;
            }
#pragma unroll
        for (int o = 16; o; o >>= 1) sum += __shfl_xor_sync(0xffffffffu, sum, o);
        float inv = 1.0f / sum;
#pragma unroll
        for (int r = 0; r < RN; r++) {
            float* srow = &g_sc[b][r][srs[r]][0];
#pragma unroll
            for (int c = 0; c < 8; c++) srow[c * 32 + lane] = adj[r][c] * inv;
        }
    }
}

// ---------------- K5: bf16-split mma.sync p @ v_sorted ----------------
// smem: vT hi [64][VSTR] bf16 + vT lo. p fragments loaded from gmem (L2-hot).
#define SM5_TOTAL (2 * 64 * VSTR * 2)

__global__ void __launch_bounds__(512) k_av(const float* __restrict__ v) {
    int n = blockIdx.x, r = blockIdx.y, b = blockIdx.z;
    extern __shared__ char sm5[];
    __nv_bfloat16* vh = (__nv_bfloat16*)sm5;
    __nv_bfloat16* vl = vh + 64 * VSTR;
    int tid = threadIdx.x;
    int prevbase = ((n + NB2 - 1) & (NB2 - 1)) * CH;

    // stage vT: row = d, col = j (pairs packed in uint32, low half = even j)
    for (int idx = tid; idx < 128 * 16; idx += 512) {
        int jp = idx & 127, f = idx >> 7;   // jp: j-pair, f: 4-d group
        int ja = 2 * jp, jb = 2 * jp + 1;
        int kpa = (ja < CH) ? (prevbase + ja) : (n * CH + ja - CH);
        int kpb = (jb < CH) ? (prevbase + jb) : (n * CH + jb - CH);
        int kia = g_hidx[b][r][kpa];
        int kib = g_hidx[b][r][kpb];
        float4 va = *(const float4*)&v[((size_t)b * LEN + kia) * DIM + f * 4];
        float4 vb = *(const float4*)&v[((size_t)b * LEN + kib) * DIM + f * 4];
        float pa[4] = {va.x, va.y, va.z, va.w};
        float pb[4] = {vb.x, vb.y, vb.z, vb.w};
#pragma unroll
        for (int c = 0; c < 4; c++) {
            uint2 s = split2(make_float2(pa[c], pb[c]));
            *(uint32_t*)&vh[(f * 4 + c) * VSTR + 2 * jp] = s.x;
            *(uint32_t*)&vl[(f * 4 + c) * VSTR + 2 * jp] = s.y;
        }
    }
    __syncthreads();

    int wid = tid >> 5, lane = tid & 31;
    int wm = wid >> 1, wn = wid & 1;
    int i0 = wm * 16, d0 = wn * 32;
    int g = lane >> 2, t4 = lane & 3;

    float acc[4][4];
#pragma unroll
    for (int nt = 0; nt < 4; nt++)
#pragma unroll
        for (int c = 0; c < 4; c++) acc[nt][c] = 0.f;

    const float* pA0 = &g_sc[b][r][n * CH + i0 + g][0];
    const float* pA8 = &g_sc[b][r][n * CH + i0 + g + 8][0];
#pragma unroll 4
    for (int ks = 0; ks < 16; ks++) {
        int k0 = ks * 16 + 2 * t4;
        uint2 s0 = split2(*(const float2*)&pA0[k0]);
        uint2 s1 = split2(*(const float2*)&pA8[k0]);
        uint2 s2 = split2(*(const float2*)&pA0[k0 + 8]);
        uint2 s3 = split2(*(const float2*)&pA8[k0 + 8]);
        uint32_t ah[4] = {s0.x, s1.x, s2.x, s3.x};
        uint32_t al[4] = {s0.y, s1.y, s2.y, s3.y};
#pragma unroll
        for (int nt = 0; nt < 4; nt++) {
            int rowb = (d0 + nt * 8 + g) * VSTR + ks * 16;
            uint32_t bh0 = *(const uint32_t*)&vh[rowb + 2 * t4];
            uint32_t bh1 = *(const uint32_t*)&vh[rowb + 2 * t4 + 8];
            uint32_t bl0 = *(const uint32_t*)&vl[rowb + 2 * t4];
            uint32_t bl1 = *(const uint32_t*)&vl[rowb + 2 * t4 + 8];
            mma_bf16(acc[nt], ah, bh0, bh1);
            mma_bf16(acc[nt], ah, bl0, bl1);
            mma_bf16(acc[nt], al, bh0, bh1);
        }
    }

    int ia = i0 + g, ib = ia + 8;
#pragma unroll
    for (int nt = 0; nt < 4; nt++) {
        int d = d0 + nt * 8 + 2 * t4;
        *(float2*)&g_attn[b][r][n * CH + ia][d] = make_float2(acc[nt][0], acc[nt][1]);
        *(float2*)&g_attn[b][r][n * CH + ib][d] = make_float2(acc[nt][2], acc[nt][3]);
    }
}

// ---------------- K6: gather rounds back to original order, sum ----------------
__global__ void __launch_bounds__(256) k_out(float* __restrict__ out) {
    int gid = blockIdx.x * 256 + threadIdx.x;
    int dq = gid & 15;
    int l = (gid >> 4) & (LEN - 1);
    int b = gid >> 15;
    float4 s = make_float4(0.f, 0.f, 0.f, 0.f);
#pragma unroll
    for (int r = 0; r < RN; r++) {
        int sIdx = g_oidx[b][r][l];
        float4 a = *(const float4*)&g_attn[b][r][sIdx][dq * 4];
        s.x += a.x; s.y += a.y; s.z += a.z; s.w += a.w;
    }
    *(float4*)&out[((size_t)b * LEN + l) * DIM + dq * 4] = s;
}

// ---------------- launch ----------------
extern "C" void kernel_launch(void* const* d_in, const int* in_sizes, int n_in,
                              void* d_out, int out_size) {
    const float* q  = (const float*)d_in[0];
    const float* v  = (const float*)d_in[1];
    const float* rm = (const float*)d_in[2];
    float* out = (float*)d_out;

    cudaFuncSetAttribute(k_scores, cudaFuncAttributeMaxDynamicSharedMemorySize, SM3_TOTAL);
    cudaFuncSetAttribute(k_av,     cudaFuncAttributeMaxDynamicSharedMemorySize, SM5_TOTAL);

    k_rmn<<<BHN, 64>>>(rm);
    k_hash<<<dim3(LEN / 128, BHN), 128>>>(q);
    k_sort<<<BHN * RN, 256>>>();
    k_pack<<<BHN * LEN / 256, 256>>>();
    k_scores<<<dim3(NB2, RN, BHN), 512, SM3_TOTAL>>>();
    k_softmax<<<dim3(LEN / 256, BHN), 512>>>();
    k_av<<<dim3(NB2, RN, BHN), 512, SM5_TOTAL>>>(v);
    k_out<<<(BHN * LEN * 16) / 256, 256>>>(out);
}

// round 10
// speedup vs baseline: 1.7470x; 1.0047x over previous
#include <cuda_runtime.h>
#include <cuda_bf16.h>
#include <stdint.h>

#define BHN 16
#define LEN 2048
#define DIM 64
#define RN  4
#define NB2 16
#define CH  128
#define NK  256
#define XSTR 72    // k_scores staged row stride (bf16)
#define VSTR 264   // k_av vT row stride (bf16)

typedef unsigned long long ull;

// ---------------- scratch (device globals; allocation-free) ----------------
__device__ float  g_qn  [BHN][LEN][DIM];
__device__ float  g_rmn [BHN][DIM][64];
__device__ int    g_hash[BHN][RN][LEN];
__device__ int    g_hidx[BHN][RN][LEN];
__device__ int    g_oidx[BHN][RN][LEN];
__device__ float  g_sc  [BHN][RN][LEN][NK];  // adjusted scores, then p (in-place)
__device__ float  g_attn[BHN][RN][LEN][DIM];

__constant__ float c_log4[4] = {0.0f, 0.6931471805599453f, 1.0986122886681098f, 1.3862943611198906f};

// fast exp on the FMA pipe — R2's exact version
__device__ __forceinline__ float fexp(float x) {
    x = fmaxf(x, -87.0f);
    float t = fmaf(x, 1.4426950408889634f, 12582912.0f);
    int n = __float_as_int(t) - 0x4B400000;
    float fi = t - 12582912.0f;
    float z = fmaf(fi, -0.6931471805599453f, x);
    float p = 8.3333337e-3f;
    p = fmaf(p, z, 4.1666668e-2f);
    p = fmaf(p, z, 0.16666667f);
    p = fmaf(p, z, 0.5f);
    p = fmaf(p, z, 1.0f);
    p = fmaf(p, z, 1.0f);
    return p * __int_as_float((n + 127) << 23);
}

// ---------------- mma.sync bf16 m16n8k16 ----------------
__device__ __forceinline__ void mma_bf16(float* c, const uint32_t* a, uint32_t b0, uint32_t b1) {
    asm volatile(
        "mma.sync.aligned.m16n8k16.row.col.f32.bf16.bf16.f32 "
        "{%0,%1,%2,%3}, {%4,%5,%6,%7}, {%8,%9}, {%0,%1,%2,%3};"
        : "+f"(c[0]), "+f"(c[1]), "+f"(c[2]), "+f"(c[3])
        : "r"(a[0]), "r"(a[1]), "r"(a[2]), "r"(a[3]), "r"(b0), "r"(b1));
}

// split float2 -> packed bf16 hi (x) and lo (y); low half = .x
__device__ __forceinline__ uint2 split2(float2 f) {
    __nv_bfloat16 h0 = __float2bfloat16(f.x);
    __nv_bfloat16 h1 = __float2bfloat16(f.y);
    __nv_bfloat16 l0 = __float2bfloat16(f.x - __bfloat162float(h0));
    __nv_bfloat16 l1 = __float2bfloat16(f.y - __bfloat162float(h1));
    uint2 r;
    r.x = ((uint32_t)__bfloat16_as_ushort(h1) << 16) | __bfloat16_as_ushort(h0);
    r.y = ((uint32_t)__bfloat16_as_ushort(l1) << 16) | __bfloat16_as_ushort(l0);
    return r;
}

// ---------------- K0: normalize rand_matrix columns ----------------
__global__ void k_rmn(const float* __restrict__ rm) {
    int b = blockIdx.x;
    int j = threadIdx.x;
    float s = 0.f;
    for (int d = 0; d < DIM; d++) {
        float v = rm[(size_t)(b * DIM + d) * 64 + j];
        s += v * v;
    }
    float inv = rsqrtf(s);
    for (int d = 0; d < DIM; d++)
        g_rmn[b][d][j] = rm[(size_t)(b * DIM + d) * 64 + j] * inv;
}

// ---------------- K1: normalize q + hashes ----------------
__global__ void __launch_bounds__(128) k_hash(const float* __restrict__ q) {
    int b = blockIdx.y;
    __shared__ float s_rm[DIM * 64];
    int tid = threadIdx.x;
    const float4* rsrc = (const float4*)&g_rmn[b][0][0];
    for (int t = tid; t < DIM * 64 / 4; t += 128) ((float4*)s_rm)[t] = rsrc[t];
    __syncthreads();

    int l = blockIdx.x * 128 + tid;
    float qv[DIM];
    const float4* qp = (const float4*)&q[((size_t)b * LEN + l) * DIM];
#pragma unroll
    for (int t = 0; t < 16; t++) {
        float4 v = qp[t];
        qv[4 * t] = v.x; qv[4 * t + 1] = v.y; qv[4 * t + 2] = v.z; qv[4 * t + 3] = v.w;
    }
    float ss = 0.f;
#pragma unroll
    for (int d = 0; d < DIM; d++) ss += qv[d] * qv[d];
    float inv = rsqrtf(ss);
#pragma unroll
    for (int d = 0; d < DIM; d++) qv[d] *= inv;
    float4* qd = (float4*)&g_qn[b][l][0];
#pragma unroll
    for (int t = 0; t < 16; t++)
        qd[t] = make_float4(qv[4 * t], qv[4 * t + 1], qv[4 * t + 2], qv[4 * t + 3]);

    for (int r = 0; r < RN; r++) {
        float bp = -1e30f, bn = -1e30f;
        int bpi = 0, bni = 0;
        for (int k = 0; k < 16; k++) {
            float acc = 0.f;
#pragma unroll
            for (int d = 0; d < DIM; d++) acc += qv[d] * s_rm[d * 64 + r * 16 + k];
            if (acc > bp)  { bp = acc;  bpi = k; }
            if (-acc > bn) { bn = -acc; bni = k; }
        }
        g_hash[b][r][l] = (bn > bp) ? (16 + bni) : bpi;
    }
}

// ---------------- K2: stable counting sort per (b,r) ----------------
__global__ void __launch_bounds__(256) k_sort() {
    int b = blockIdx.x >> 2, r = blockIdx.x & 3;
    __shared__ int hist[32][257];
    __shared__ int base[32];
    int t = threadIdx.x;
#pragma unroll
    for (int v = 0; v < 32; v++) hist[v][t] = 0;
    __syncthreads();
    int h[8];
#pragma unroll
    for (int e = 0; e < 8; e++) {
        h[e] = g_hash[b][r][t * 8 + e];
        hist[h[e]][t]++;
    }
    __syncthreads();
    if (t < 32) {
        int run = 0;
        for (int i = 0; i < 256; i++) { int x = hist[t][i]; hist[t][i] = run; run += x; }
        base[t] = run;
    }
    __syncthreads();
    if (t == 0) {
        int run = 0;
        for (int v = 0; v < 32; v++) { int x = base[v]; base[v] = run; run += x; }
    }
    __syncthreads();
#pragma unroll
    for (int e = 0; e < 8; e++) {
        int l = t * 8 + e, v = h[e];
        int off = hist[v][t];
        hist[v][t] = off + 1;
        int pos = base[v] + off;
        g_hidx[b][r][pos] = l;
        g_oidx[b][r][l] = pos;
    }
}

// ---------------- K3: bf16-split mma.sync score GEMM + packed-meta epilogue ----------------
// smem: kmeta int2[256] @0 (2048B), xh @4096 (256*72 bf16), xl after. total 77824B
#define SM3_TOTAL (4096 + 2 * NK * XSTR * 2)

__global__ void __launch_bounds__(512) k_scores() {
    int n = blockIdx.x, r = blockIdx.y, b = blockIdx.z;
    extern __shared__ char sm3[];
    int2* kmeta = (int2*)sm3;   // .x = (khash<<16)|kidx, .y = packed chunk per round
    __nv_bfloat16* xh = (__nv_bfloat16*)(sm3 + 4096);
    __nv_bfloat16* xl = (__nv_bfloat16*)(sm3 + 4096 + NK * XSTR * 2);
    int tid = threadIdx.x;
    int prevbase = ((n + NB2 - 1) & (NB2 - 1)) * CH;

    for (int j = tid; j < NK; j += 512) {
        int keypos = (j < CH) ? (prevbase + j) : (n * CH + j - CH);
        int ki = g_hidx[b][r][keypos];
        int kh = g_hash[b][r][ki];
        int pc = 0;
#pragma unroll
        for (int rr = 0; rr < RN; rr++)
            pc |= ((g_oidx[b][rr][ki] >> 7) & 15) << (8 * rr);
        kmeta[j] = make_int2((kh << 16) | ki, pc);
    }
    __syncthreads();

    for (int t = tid; t < NK * 16; t += 512) {
        int row = t >> 4, cg = t & 15;
        int ki = kmeta[row].x & 0xFFFF;
        float4 v = *(const float4*)&g_qn[b][ki][cg * 4];
        uint2 p0 = split2(make_float2(v.x, v.y));
        uint2 p1 = split2(make_float2(v.z, v.w));
        *(uint2*)&xh[row * XSTR + cg * 4] = make_uint2(p0.x, p1.x);
        *(uint2*)&xl[row * XSTR + cg * 4] = make_uint2(p0.y, p1.y);
    }
    __syncthreads();

    int wid = tid >> 5, lane = tid & 31;
    int wm = wid >> 1, wn = wid & 1;
    int i0 = wm * 16, j0 = wn * 128;
    int g = lane >> 2, t4 = lane & 3;

    float acc[16][4];
#pragma unroll
    for (int nt = 0; nt < 16; nt++)
#pragma unroll
        for (int c = 0; c < 4; c++) acc[nt][c] = 0.f;

    const __nv_bfloat16* Ah = xh + (CH + i0) * XSTR;
    const __nv_bfloat16* Al = xl + (CH + i0) * XSTR;
#pragma unroll
    for (int ks = 0; ks < 4; ks++) {
        int k0 = ks * 16 + 2 * t4;
        uint32_t ah[4], al[4];
        ah[0] = *(const uint32_t*)&Ah[g * XSTR + k0];
        ah[1] = *(const uint32_t*)&Ah[(g + 8) * XSTR + k0];
        ah[2] = *(const uint32_t*)&Ah[g * XSTR + k0 + 8];
        ah[3] = *(const uint32_t*)&Ah[(g + 8) * XSTR + k0 + 8];
        al[0] = *(const uint32_t*)&Al[g * XSTR + k0];
        al[1] = *(const uint32_t*)&Al[(g + 8) * XSTR + k0];
        al[2] = *(const uint32_t*)&Al[g * XSTR + k0 + 8];
        al[3] = *(const uint32_t*)&Al[(g + 8) * XSTR + k0 + 8];
#pragma unroll
        for (int nt = 0; nt < 16; nt++) {
            int rowb = (j0 + nt * 8 + g) * XSTR + k0;
            uint32_t bh0 = *(const uint32_t*)&xh[rowb];
            uint32_t bh1 = *(const uint32_t*)&xh[rowb + 8];
            uint32_t bl0 = *(const uint32_t*)&xl[rowb];
            uint32_t bl1 = *(const uint32_t*)&xl[rowb + 8];
            mma_bf16(acc[nt], ah, bh0, bh1);
            mma_bf16(acc[nt], ah, bl0, bl1);
            mma_bf16(acc[nt], al, bh0, bh1);
        }
    }

    int ia = i0 + g, ib = i0 + g + 8;
    int2 qa = kmeta[CH + ia], qb = kmeta[CH + ib];
    int qidxa = qa.x & 0xFFFF, qha = qa.x >> 16, npa = qa.y;
    int qidxb = qb.x & 0xFFFF, qhb = qb.x >> 16, npb = qb.y;
    int ppa = ((npa | 0x10101010) - 0x01010101) & 0x0f0f0f0f;
    int ppb = ((npb | 0x10101010) - 0x01010101) & 0x0f0f0f0f;
    float* rowa = &g_sc[b][r][n * CH + ia][0];
    float* rowb = &g_sc[b][r][n * CH + ib][0];
#pragma unroll
    for (int nt = 0; nt < 16; nt++) {
        int j = j0 + nt * 8 + 2 * t4;          // even -> int4 aligned
        int4 km = *(const int4*)&kmeta[j];
        int kj0 = km.x & 0xFFFF, kh0 = km.x >> 16, kc0 = km.y;
        int kj1 = km.z & 0xFFFF, kh1 = km.z >> 16, kc1 = km.w;
        float o00 = acc[nt][0] * 0.125f, o01 = acc[nt][1] * 0.125f;
        float o10 = acc[nt][2] * 0.125f, o11 = acc[nt][3] * 0.125f;
        if (qidxa == kj0)                      o00 = -100000.0f;
        else if (qidxa < kj0 || qha != kh0)    o00 = -1000000000.0f;
        if (qidxa == kj1)                      o01 = -100000.0f;
        else if (qidxa < kj1 || qha != kh1)    o01 = -1000000000.0f;
        if (qidxb == kj0)                      o10 = -100000.0f;
        else if (qidxb < kj0 || qhb != kh0)    o10 = -1000000000.0f;
        if (qidxb == kj1)                      o11 = -100000.0f;
        else if (qidxb < kj1 || qhb != kh1)    o11 = -1000000000.0f;
        unsigned m;
        m = __vcmpeq4((unsigned)kc0, (unsigned)npa) | __vcmpeq4((unsigned)kc0, (unsigned)ppa);
        o00 -= c_log4[(__popc(m) >> 3) - 1];
        m = __vcmpeq4((unsigned)kc1, (unsigned)npa) | __vcmpeq4((unsigned)kc1, (unsigned)ppa);
        o01 -= c_log4[(__popc(m) >> 3) - 1];
        m = __vcmpeq4((unsigned)kc0, (unsigned)npb) | __vcmpeq4((unsigned)kc0, (unsigned)ppb);
        o10 -= c_log4[(__popc(m) >> 3) - 1];
        m = __vcmpeq4((unsigned)kc1, (unsigned)npb) | __vcmpeq4((unsigned)kc1, (unsigned)ppb);
        o11 -= c_log4[(__popc(m) >> 3) - 1];
        *(float2*)&rowa[j] = make_float2(o00, o01);
        *(float2*)&rowb[j] = make_float2(o10, o11);
    }
}

// ---------------- K4: joint softmax (in-place, float4 lanes) ----------------
__global__ void __launch_bounds__(512) k_softmax() {
    int b = blockIdx.y;
    int warp = threadIdx.x >> 5, lane = threadIdx.x & 31;
#pragma unroll 1
    for (int it = 0; it < 16; it++) {
        int l = blockIdx.x * 256 + it * 16 + warp;
        int srs[RN];
        float4 adj[RN][2];
        float mx = -3.4e38f;
#pragma unroll
        for (int r = 0; r < RN; r++) {
            srs[r] = g_oidx[b][r][l];
            const float4* srow = (const float4*)&g_sc[b][r][srs[r]][0];
            adj[r][0] = srow[lane];
            adj[r][1] = srow[lane + 32];
#pragma unroll
            for (int h = 0; h < 2; h++) {
                mx = fmaxf(mx, fmaxf(fmaxf(adj[r][h].x, adj[r][h].y),
                                     fmaxf(adj[r][h].z, adj[r][h].w)));
            }
        }
#pragma unroll
        for (int o = 16; o; o >>= 1) mx = fmaxf(mx, __shfl_xor_sync(0xffffffffu, mx, o));
        float sum = 0.f;
#pragma unroll
        for (int r = 0; r < RN; r++)
#pragma unroll
            for (int h = 0; h < 2; h++) {
                adj[r][h].x = fexp(adj[r][h].x - mx);
                adj[r][h].y = fexp(adj[r][h].y - mx);
                adj[r][h].z = fexp(adj[r][h].z - mx);
                adj[r][h].w = fexp(adj[r][h].w - mx);
                sum += adj[r][h].x + adj[r][h].y + adj[r][h].z + adj[r][h].w;
            }
#pragma unroll
        for (int o = 16; o; o >>= 1) sum += __shfl_xor_sync(0xffffffffu, sum, o);
        float inv = 1.0f / sum;
#pragma unroll
        for (int r = 0; r < RN; r++) {
            float4* srow = (float4*)&g_sc[b][r][srs[r]][0];
#pragma unroll
            for (int h = 0; h < 2; h++) {
                float4 w = adj[r][h];
                w.x *= inv; w.y *= inv; w.z *= inv; w.w *= inv;
                srow[lane + h * 32] = w;
            }
        }
    }
}

// ---------------- K5: bf16-split mma.sync p @ v_sorted (R9 verbatim) ----------------
#define SM5_TOTAL (2 * 64 * VSTR * 2)

__global__ void __launch_bounds__(512) k_av(const float* __restrict__ v) {
    int n = blockIdx.x, r = blockIdx.y, b = blockIdx.z;
    extern __shared__ char sm5[];
    __nv_bfloat16* vh = (__nv_bfloat16*)sm5;
    __nv_bfloat16* vl = vh + 64 * VSTR;
    int tid = threadIdx.x;
    int prevbase = ((n + NB2 - 1) & (NB2 - 1)) * CH;

    for (int idx = tid; idx < 128 * 16; idx += 512) {
        int jp = idx & 127, f = idx >> 7;
        int ja = 2 * jp, jb = 2 * jp + 1;
        int kpa = (ja < CH) ? (prevbase + ja) : (n * CH + ja - CH);
        int kpb = (jb < CH) ? (prevbase + jb) : (n * CH + jb - CH);
        int kia = g_hidx[b][r][kpa];
        int kib = g_hidx[b][r][kpb];
        float4 va = *(const float4*)&v[((size_t)b * LEN + kia) * DIM + f * 4];
        float4 vb = *(const float4*)&v[((size_t)b * LEN + kib) * DIM + f * 4];
        float pa[4] = {va.x, va.y, va.z, va.w};
        float pb[4] = {vb.x, vb.y, vb.z, vb.w};
#pragma unroll
        for (int c = 0; c < 4; c++) {
            uint2 s = split2(make_float2(pa[c], pb[c]));
            *(uint32_t*)&vh[(f * 4 + c) * VSTR + 2 * jp] = s.x;
            *(uint32_t*)&vl[(f * 4 + c) * VSTR + 2 * jp] = s.y;
        }
    }
    __syncthreads();

    int wid = tid >> 5, lane = tid & 31;
    int wm = wid >> 1, wn = wid & 1;
    int i0 = wm * 16, d0 = wn * 32;
    int g = lane >> 2, t4 = lane & 3;

    float acc[4][4];
#pragma unroll
    for (int nt = 0; nt < 4; nt++)
#pragma unroll
        for (int c = 0; c < 4; c++) acc[nt][c] = 0.f;

    const float* pA0 = &g_sc[b][r][n * CH + i0 + g][0];
    const float* pA8 = &g_sc[b][r][n * CH + i0 + g + 8][0];
#pragma unroll 4
    for (int ks = 0; ks < 16; ks++) {
        int k0 = ks * 16 + 2 * t4;
        uint2 s0 = split2(*(const float2*)&pA0[k0]);
        uint2 s1 = split2(*(const float2*)&pA8[k0]);
        uint2 s2 = split2(*(const float2*)&pA0[k0 + 8]);
        uint2 s3 = split2(*(const float2*)&pA8[k0 + 8]);
        uint32_t ah[4] = {s0.x, s1.x, s2.x, s3.x};
        uint32_t al[4] = {s0.y, s1.y, s2.y, s3.y};
#pragma unroll
        for (int nt = 0; nt < 4; nt++) {
            int rowb = (d0 + nt * 8 + g) * VSTR + ks * 16;
            uint32_t bh0 = *(const uint32_t*)&vh[rowb + 2 * t4];
            uint32_t bh1 = *(const uint32_t*)&vh[rowb + 2 * t4 + 8];
            uint32_t bl0 = *(const uint32_t*)&vl[rowb + 2 * t4];
            uint32_t bl1 = *(const uint32_t*)&vl[rowb + 2 * t4 + 8];
            mma_bf16(acc[nt], ah, bh0, bh1);
            mma_bf16(acc[nt], ah, bl0, bl1);
            mma_bf16(acc[nt], al, bh0, bh1);
        }
    }

    int ia = i0 + g, ib = ia + 8;
#pragma unroll
    for (int nt = 0; nt < 4; nt++) {
        int d = d0 + nt * 8 + 2 * t4;
        *(float2*)&g_attn[b][r][n * CH + ia][d] = make_float2(acc[nt][0], acc[nt][1]);
        *(float2*)&g_attn[b][r][n * CH + ib][d] = make_float2(acc[nt][2], acc[nt][3]);
    }
}

// ---------------- K6: gather rounds back to original order, sum ----------------
__global__ void __launch_bounds__(256) k_out(float* __restrict__ out) {
    int gid = blockIdx.x * 256 + threadIdx.x;
    int dq = gid & 15;
    int l = (gid >> 4) & (LEN - 1);
    int b = gid >> 15;
    float4 s = make_float4(0.f, 0.f, 0.f, 0.f);
#pragma unroll
    for (int r = 0; r < RN; r++) {
        int sIdx = g_oidx[b][r][l];
        float4 a = *(const float4*)&g_attn[b][r][sIdx][dq * 4];
        s.x += a.x; s.y += a.y; s.z += a.z; s.w += a.w;
    }
    *(float4*)&out[((size_t)b * LEN + l) * DIM + dq * 4] = s;
}

// ---------------- launch ----------------
extern "C" void kernel_launch(void* const* d_in, const int* in_sizes, int n_in,
                              void* d_out, int out_size) {
    const float* q  = (const float*)d_in[0];
    const float* v  = (const float*)d_in[1];
    const float* rm = (const float*)d_in[2];
    float* out = (float*)d_out;

    cudaFuncSetAttribute(k_scores, cudaFuncAttributeMaxDynamicSharedMemorySize, SM3_TOTAL);
    cudaFuncSetAttribute(k_av,     cudaFuncAttributeMaxDynamicSharedMemorySize, SM5_TOTAL);

    k_rmn<<<BHN, 64>>>(rm);
    k_hash<<<dim3(LEN / 128, BHN), 128>>>(q);
    k_sort<<<BHN * RN, 256>>>();
    k_scores<<<dim3(NB2, RN, BHN), 512, SM3_TOTAL>>>();   // launch #3 -> ncu slot
    k_softmax<<<dim3(LEN / 256, BHN), 512>>>();
    k_av<<<dim3(NB2, RN, BHN), 512, SM5_TOTAL>>>(v);
    k_out<<<(BHN * LEN * 16) / 256, 256>>>(out);
}